// round 9
// baseline (speedup 1.0000x reference)
#include <cuda_runtime.h>
#include <cuda_bf16.h>
#include <math.h>

// ---------------- dims ----------------
#define BATCH 4
#define SEQ   2048
#define DM    768
#define DI    1536
#define DS    16
#define DR    48
#define MROWS (BATCH*SEQ)   // 8192
#define NPROJ 80            // DR + 2*DS

// ------------- scratch (device globals; referenced directly in kernels,
// ------------- so kernel_launch needs NO host-side symbol lookups) --------
__device__ float g_u   [(size_t)MROWS*DM];     // LN output
__device__ float g_xz  [(size_t)MROWS*2*DI];   // in_proj output (xs | z)
__device__ float g_xc  [(size_t)MROWS*DI];     // conv+silu output
__device__ float g_proj[(size_t)MROWS*NPROJ];  // x_proj output (dt_r | B | C)
__device__ float g_dt  [(size_t)MROWS*DI];     // softplus(dt_proj)
__device__ float g_yg  [(size_t)MROWS*DI];     // gated scan output

// ================= kernel 1: res=res+x, LayerNorm -> g_u ==================
__global__ __launch_bounds__(256) void add_ln_kernel(
    const float* __restrict__ x, const float* __restrict__ res,
    const float* __restrict__ gamma, const float* __restrict__ beta,
    float* __restrict__ res_out) {
  int row = blockIdx.x;
  int tid = threadIdx.x;
  const float* xr = x   + (size_t)row * DM;
  const float* rr = res + (size_t)row * DM;
  float v[3];
  float s = 0.f, ss = 0.f;
#pragma unroll
  for (int i = 0; i < 3; i++) {
    int c = tid + i * 256;
    float t = xr[c] + rr[c];
    v[i] = t; s += t; ss += t * t;
  }
  __shared__ float red0[8], red1[8];
#pragma unroll
  for (int o = 16; o; o >>= 1) {
    s  += __shfl_xor_sync(0xffffffffu, s,  o);
    ss += __shfl_xor_sync(0xffffffffu, ss, o);
  }
  if ((tid & 31) == 0) { red0[tid >> 5] = s; red1[tid >> 5] = ss; }
  __syncthreads();
  if (tid < 32) {
    float a = (tid < 8) ? red0[tid] : 0.f;
    float b = (tid < 8) ? red1[tid] : 0.f;
#pragma unroll
    for (int o = 4; o; o >>= 1) {
      a += __shfl_xor_sync(0xffffffffu, a, o);
      b += __shfl_xor_sync(0xffffffffu, b, o);
    }
    if (tid == 0) { red0[0] = a; red1[0] = b; }
  }
  __syncthreads();
  float mean = red0[0] * (1.f / DM);
  float var  = red1[0] * (1.f / DM) - mean * mean;
  float rstd = rsqrtf(var + 1e-5f);
  float* ro = res_out + (size_t)row * DM;
  float* uo = g_u     + (size_t)row * DM;
#pragma unroll
  for (int i = 0; i < 3; i++) {
    int c = tid + i * 256;
    ro[c] = v[i];
    uo[c] = (v[i] - mean) * rstd * gamma[c] + beta[c];
  }
}

// ================= SGEMM (NT: both row-major, K inner) ====================
// C[M,N] = A[M,K] * B[N,K]^T.  M,N multiples of 128, K multiple of 8.
__global__ __launch_bounds__(256) void sgemm_nt_128(
    const float* __restrict__ A, const float* __restrict__ B,
    float* __restrict__ C, int N, int K) {
  __shared__ float As[8][128];
  __shared__ float Bs[8][128];
  int tid  = threadIdx.x;
  int bm   = blockIdx.y << 7;
  int bn   = blockIdx.x << 7;
  int arow = tid >> 1;
  int acol = (tid & 1) << 2;
  int tx   = tid & 15, ty = tid >> 4;
  const float* Ag = A + (size_t)(bm + arow) * K + acol;
  const float* Bg = B + (size_t)(bn + arow) * K + acol;
  float acc[8][8];
#pragma unroll
  for (int i = 0; i < 8; i++)
#pragma unroll
    for (int j = 0; j < 8; j++) acc[i][j] = 0.f;

  for (int k0 = 0; k0 < K; k0 += 8) {
    float4 av = *(const float4*)(Ag + k0);
    float4 bv = *(const float4*)(Bg + k0);
    As[acol + 0][arow] = av.x; As[acol + 1][arow] = av.y;
    As[acol + 2][arow] = av.z; As[acol + 3][arow] = av.w;
    Bs[acol + 0][arow] = bv.x; Bs[acol + 1][arow] = bv.y;
    Bs[acol + 2][arow] = bv.z; Bs[acol + 3][arow] = bv.w;
    __syncthreads();
#pragma unroll
    for (int kk = 0; kk < 8; kk++) {
      float ra[8], rb[8];
      *(float4*)&ra[0] = *(const float4*)&As[kk][ty << 3];
      *(float4*)&ra[4] = *(const float4*)&As[kk][(ty << 3) + 4];
      *(float4*)&rb[0] = *(const float4*)&Bs[kk][tx << 3];
      *(float4*)&rb[4] = *(const float4*)&Bs[kk][(tx << 3) + 4];
#pragma unroll
      for (int i = 0; i < 8; i++)
#pragma unroll
        for (int j = 0; j < 8; j++)
          acc[i][j] = fmaf(ra[i], rb[j], acc[i][j]);
    }
    __syncthreads();
  }
#pragma unroll
  for (int i = 0; i < 8; i++) {
    float4 v0 = make_float4(acc[i][0], acc[i][1], acc[i][2], acc[i][3]);
    float4 v1 = make_float4(acc[i][4], acc[i][5], acc[i][6], acc[i][7]);
    float* Cp = C + (size_t)(bm + (ty << 3) + i) * N + bn + (tx << 3);
    *(float4*)Cp       = v0;
    *(float4*)(Cp + 4) = v1;
  }
}

// ============ kernel 3: causal depthwise conv1d (k=4) + SiLU ==============
__global__ __launch_bounds__(256) void conv_silu_kernel(
    const float* __restrict__ cw, const float* __restrict__ cb) {
  int d  = blockIdx.y * 256 + threadIdx.x;         // 0..1535
  int ch = blockIdx.x;                              // 0..(BATCH*SEQ/16 - 1)
  int b  = ch >> 7;
  int t0 = (ch & 127) << 4;
  float w0 = cw[d * 4 + 0], w1 = cw[d * 4 + 1];
  float w2 = cw[d * 4 + 2], w3 = cw[d * 4 + 3];
  float bb = cb[d];
  size_t base = ((size_t)b * SEQ) * (2 * DI) + d;   // xs slice of g_xz
  float xm3 = (t0 >= 3) ? g_xz[base + (size_t)(t0 - 3) * (2 * DI)] : 0.f;
  float xm2 = (t0 >= 2) ? g_xz[base + (size_t)(t0 - 2) * (2 * DI)] : 0.f;
  float xm1 = (t0 >= 1) ? g_xz[base + (size_t)(t0 - 1) * (2 * DI)] : 0.f;
#pragma unroll
  for (int i = 0; i < 16; i++) {
    int t = t0 + i;
    float xt = g_xz[base + (size_t)t * (2 * DI)];
    float a  = w0 * xm3 + w1 * xm2 + w2 * xm1 + w3 * xt + bb;
    float sg = 1.f / (1.f + __expf(-a));
    g_xc[((size_t)b * SEQ + t) * DI + d] = a * sg;
    xm3 = xm2; xm2 = xm1; xm1 = xt;
  }
}

// ====== kernel 4: x_proj: proj[M,80] = xc[M,1536] @ W_xproj[80,1536]^T ====
__global__ __launch_bounds__(256) void xproj_kernel(
    const float* __restrict__ W) {
  __shared__ float sA[64][17];   // [row][kk]
  __shared__ float sB[80][17];   // [n][kk]
  int tid = threadIdx.x;
  int tx = tid & 15, ty = tid >> 4;
  int bm = blockIdx.x * 64;
  int kk = tid & 15, r = tid >> 4;
  float acc[4][5];
#pragma unroll
  for (int i = 0; i < 4; i++)
#pragma unroll
    for (int j = 0; j < 5; j++) acc[i][j] = 0.f;

  for (int k0 = 0; k0 < DI; k0 += 16) {
#pragma unroll
    for (int p = 0; p < 4; p++)
      sA[r + 16 * p][kk] = g_xc[(size_t)(bm + r + 16 * p) * DI + k0 + kk];
#pragma unroll
    for (int q = 0; q < 5; q++)
      sB[r + 16 * q][kk] = W[(size_t)(r + 16 * q) * DI + k0 + kk];
    __syncthreads();
#pragma unroll
    for (int k = 0; k < 16; k++) {
      float ra[4], rb[5];
#pragma unroll
      for (int i = 0; i < 4; i++) ra[i] = sA[ty * 4 + i][k];
#pragma unroll
      for (int j = 0; j < 5; j++) rb[j] = sB[tx + 16 * j][k];
#pragma unroll
      for (int i = 0; i < 4; i++)
#pragma unroll
        for (int j = 0; j < 5; j++)
          acc[i][j] = fmaf(ra[i], rb[j], acc[i][j]);
    }
    __syncthreads();
  }
#pragma unroll
  for (int i = 0; i < 4; i++)
#pragma unroll
    for (int j = 0; j < 5; j++)
      g_proj[(size_t)(bm + ty * 4 + i) * NPROJ + tx + 16 * j] = acc[i][j];
}

// == kernel 5: dt[M,1536] = softplus(proj[:,0:48] @ W_dt[1536,48]^T + b_dt) =
__global__ __launch_bounds__(256) void dtproj_kernel(
    const float* __restrict__ Wdt, const float* __restrict__ bdt) {
  __shared__ float sA[64][49];
  __shared__ float sW[64][49];
  int tid = threadIdx.x;
  int tx = tid & 15, ty = tid >> 4;
  int bm = blockIdx.y * 64, bn = blockIdx.x * 64;
  for (int i = tid; i < 64 * 48; i += 256) {
    int r2 = i / 48, k = i % 48;
    sA[r2][k] = g_proj[(size_t)(bm + r2) * NPROJ + k];
    sW[r2][k] = Wdt[(size_t)(bn + r2) * DR + k];
  }
  __syncthreads();
  float acc[4][4];
#pragma unroll
  for (int i = 0; i < 4; i++)
#pragma unroll
    for (int j = 0; j < 4; j++) acc[i][j] = 0.f;
#pragma unroll 8
  for (int k = 0; k < 48; k++) {
    float ra[4], rb[4];
#pragma unroll
    for (int i = 0; i < 4; i++) ra[i] = sA[ty * 4 + i][k];
#pragma unroll
    for (int j = 0; j < 4; j++) rb[j] = sW[tx * 4 + j][k];
#pragma unroll
    for (int i = 0; i < 4; i++)
#pragma unroll
      for (int j = 0; j < 4; j++)
        acc[i][j] = fmaf(ra[i], rb[j], acc[i][j]);
  }
#pragma unroll
  for (int i = 0; i < 4; i++)
#pragma unroll
    for (int j = 0; j < 4; j++) {
      int col = bn + tx * 4 + j;
      float v = acc[i][j] + bdt[col];
      v = (v > 20.f) ? v : log1pf(__expf(v));     // softplus
      g_dt[(size_t)(bm + ty * 4 + i) * DI + col] = v;
    }
}

// ================= kernel 6: selective scan + gating ======================
#define SCAN_TT 64
__global__ __launch_bounds__(128) void scan_kernel(
    const float* __restrict__ A_log, const float* __restrict__ Dw) {
  int d = blockIdx.x * 128 + threadIdx.x;   // channel
  int b = blockIdx.y;                        // batch
  int tid = threadIdx.x;
  __shared__ float sBC[SCAN_TT][32];         // B(16) | C(16) per step

  float a[DS];
#pragma unroll
  for (int n = 0; n < DS; n++) a[n] = -expf(A_log[(size_t)d * DS + n]);
  float Dv = Dw[d];
  float h[DS];
#pragma unroll
  for (int n = 0; n < DS; n++) h[n] = 0.f;

  size_t di_base = ((size_t)b * SEQ) * DI + d;
  size_t z_base  = ((size_t)b * SEQ) * (2 * DI) + DI + d;

  // distance-2 register prefetch of dt / x / z
  float dt0 = g_dt[di_base],      x0 = g_xc[di_base],      z0 = g_xz[z_base];
  float dt1 = g_dt[di_base + DI], x1 = g_xc[di_base + DI], z1 = g_xz[z_base + 2 * DI];

  for (int t0 = 0; t0 < SEQ; t0 += SCAN_TT) {
    __syncthreads();  // protect sBC from previous chunk's readers
    for (int i = tid; i < SCAN_TT * 32; i += 128) {
      int tt = i >> 5, c = i & 31;
      sBC[tt][c] = g_proj[((size_t)b * SEQ + t0 + tt) * NPROJ + DR + c];
    }
    __syncthreads();
#pragma unroll 4
    for (int tt = 0; tt < SCAN_TT; tt++) {
      int t = t0 + tt;
      float dtc = dt0, xt = x0, zt = z0;
      dt0 = dt1; x0 = x1; z0 = z1;
      if (t + 2 < SEQ) {
        size_t o = di_base + (size_t)(t + 2) * DI;
        dt1 = g_dt[o];
        x1  = g_xc[o];
        z1  = g_xz[z_base + (size_t)(t + 2) * (2 * DI)];
      }
      float dtx = dtc * xt;
      float y0 = 0.f, y1 = 0.f;
#pragma unroll
      for (int n = 0; n < DS; n++) {
        float dA = __expf(dtc * a[n]);
        h[n] = h[n] * dA + dtx * sBC[tt][n];
        if (n & 1) y1 = fmaf(h[n], sBC[tt][16 + n], y1);
        else       y0 = fmaf(h[n], sBC[tt][16 + n], y0);
      }
      float y  = y0 + y1 + Dv * xt;
      float sg = 1.f / (1.f + __expf(-zt));
      g_yg[di_base + (size_t)t * DI] = y * (zt * sg);
    }
  }
}

// ---- tiny wrappers so the big GEMM kernel can bind scratch globals -------
__global__ __launch_bounds__(256) void sgemm_inproj(const float* __restrict__ W_in) {
  // delegates nothing: body duplicated via device function would cost regs;
  // instead we just call the generic kernel from launch with global pointers
  // resolved in DEVICE code via a pointer-publishing kernel (below).
}

// Publish device-global addresses into a device-visible pointer table so the
// generic sgemm kernel can be launched with them WITHOUT host symbol lookups.
__device__ float* g_ptrs[8];
__global__ void publish_ptrs_kernel() {
  g_ptrs[0] = g_u;
  g_ptrs[1] = g_xz;
  g_ptrs[2] = g_yg;
}
// Generic sgemm reading base pointers from the device table.
__global__ __launch_bounds__(256) void sgemm_nt_128_idx(
    int a_idx, const float* __restrict__ B_direct, int c_idx,
    float* __restrict__ C_direct, int N, int K) {
  const float* A = g_ptrs[a_idx];
  float* C = (c_idx >= 0) ? g_ptrs[c_idx] : C_direct;
  __shared__ float As[8][128];
  __shared__ float Bs[8][128];
  int tid  = threadIdx.x;
  int bm   = blockIdx.y << 7;
  int bn   = blockIdx.x << 7;
  int arow = tid >> 1;
  int acol = (tid & 1) << 2;
  int tx   = tid & 15, ty = tid >> 4;
  const float* Ag = A + (size_t)(bm + arow) * K + acol;
  const float* Bg = B_direct + (size_t)(bn + arow) * K + acol;
  float acc[8][8];
#pragma unroll
  for (int i = 0; i < 8; i++)
#pragma unroll
    for (int j = 0; j < 8; j++) acc[i][j] = 0.f;

  for (int k0 = 0; k0 < K; k0 += 8) {
    float4 av = *(const float4*)(Ag + k0);
    float4 bv = *(const float4*)(Bg + k0);
    As[acol + 0][arow] = av.x; As[acol + 1][arow] = av.y;
    As[acol + 2][arow] = av.z; As[acol + 3][arow] = av.w;
    Bs[acol + 0][arow] = bv.x; Bs[acol + 1][arow] = bv.y;
    Bs[acol + 2][arow] = bv.z; Bs[acol + 3][arow] = bv.w;
    __syncthreads();
#pragma unroll
    for (int kk = 0; kk < 8; kk++) {
      float ra[8], rb[8];
      *(float4*)&ra[0] = *(const float4*)&As[kk][ty << 3];
      *(float4*)&ra[4] = *(const float4*)&As[kk][(ty << 3) + 4];
      *(float4*)&rb[0] = *(const float4*)&Bs[kk][tx << 3];
      *(float4*)&rb[4] = *(const float4*)&Bs[kk][(tx << 3) + 4];
#pragma unroll
      for (int i = 0; i < 8; i++)
#pragma unroll
        for (int j = 0; j < 8; j++)
          acc[i][j] = fmaf(ra[i], rb[j], acc[i][j]);
    }
    __syncthreads();
  }
#pragma unroll
  for (int i = 0; i < 8; i++) {
    float4 v0 = make_float4(acc[i][0], acc[i][1], acc[i][2], acc[i][3]);
    float4 v1 = make_float4(acc[i][4], acc[i][5], acc[i][6], acc[i][7]);
    float* Cp = C + (size_t)(bm + (ty << 3) + i) * N + bn + (tx << 3);
    *(float4*)Cp       = v0;
    *(float4*)(Cp + 4) = v1;
  }
}

// ================================ launch ==================================
extern "C" void kernel_launch(void* const* d_in, const int* in_sizes, int n_in,
                              void* d_out, int out_size) {
  const float* x      = (const float*)d_in[0];
  const float* res    = (const float*)d_in[1];
  const float* gamma  = (const float*)d_in[2];
  const float* beta   = (const float*)d_in[3];
  const float* W_in   = (const float*)d_in[4];
  const float* conv_w = (const float*)d_in[5];
  const float* conv_b = (const float*)d_in[6];
  const float* W_xp   = (const float*)d_in[7];
  const float* W_dt   = (const float*)d_in[8];
  const float* b_dt   = (const float*)d_in[9];
  const float* A_log  = (const float*)d_in[10];
  const float* Dw     = (const float*)d_in[11];
  const float* W_out  = (const float*)d_in[12];

  float* outp    = (float*)d_out;                         // (B,L,DM)
  float* res_out = outp + (size_t)MROWS * DM;             // (B,L,DM)

  // NO host-side CUDA APIs besides kernel launches (graph-capture safe).
  publish_ptrs_kernel<<<1, 1>>>();
  // 1) res = res + x ; u = LN(res)
  add_ln_kernel<<<MROWS, 256>>>(x, res, gamma, beta, res_out);
  // 2) xz = u @ W_in^T           (8192 x 3072 x 768): A=g_u(0) -> C=g_xz(1)
  sgemm_nt_128_idx<<<dim3((2 * DI) / 128, MROWS / 128), 256>>>(
      0, W_in, 1, nullptr, 2 * DI, DM);
  // 3) xc = silu(causal_conv(xs))
  conv_silu_kernel<<<dim3(BATCH * SEQ / 16, DI / 256), 256>>>(conv_w, conv_b);
  // 4) proj = xc @ W_xproj^T     (8192 x 80 x 1536)
  xproj_kernel<<<MROWS / 64, 256>>>(W_xp);
  // 5) dt = softplus(proj[:,:48] @ W_dt^T + b_dt)   (8192 x 1536 x 48)
  dtproj_kernel<<<dim3(DI / 64, MROWS / 64), 256>>>(W_dt, b_dt);
  // 6) selective scan + D skip + silu(z) gating -> g_yg
  scan_kernel<<<dim3(DI / 128, BATCH), 128>>>(A_log, Dw);
  // 7) out = yg @ W_out^T        (8192 x 768 x 1536): A=g_yg(2) -> C=d_out
  sgemm_nt_128_idx<<<dim3(DM / 128, MROWS / 128), 256>>>(
      2, W_out, -1, outp, DM, DI);
}

// round 15
// speedup vs baseline: 1.5641x; 1.5641x over previous
#include <cuda_runtime.h>
#include <cuda_bf16.h>
#include <math.h>
#include <stdint.h>

// ---------------- dims ----------------
#define BATCH 4
#define SEQ   2048
#define DM    768
#define DI    1536
#define DS    16
#define DR    48
#define MROWS (BATCH*SEQ)   // 8192
#define NPROJ 80            // DR + 2*DS

// ------------- fp32 scratch (device globals) ------------------------------
__device__ float g_u   [(size_t)MROWS*DM];
__device__ float g_xz  [(size_t)MROWS*2*DI];
__device__ float g_xc  [(size_t)MROWS*DI];
__device__ float g_proj[(size_t)MROWS*NPROJ];
__device__ float g_dt  [(size_t)MROWS*DI];
__device__ float g_yg  [(size_t)MROWS*DI];

// ------------- bf16 split scratch -----------------------------------------
__device__ __align__(16) __nv_bfloat16 g_uhi   [(size_t)MROWS*DM];
__device__ __align__(16) __nv_bfloat16 g_ulo   [(size_t)MROWS*DM];
__device__ __align__(16) __nv_bfloat16 g_winhi [(size_t)2*DI*DM];
__device__ __align__(16) __nv_bfloat16 g_winlo [(size_t)2*DI*DM];
__device__ __align__(16) __nv_bfloat16 g_yghi  [(size_t)MROWS*DI];
__device__ __align__(16) __nv_bfloat16 g_yglo  [(size_t)MROWS*DI];
__device__ __align__(16) __nv_bfloat16 g_wouthi[(size_t)DM*DI];
__device__ __align__(16) __nv_bfloat16 g_woutlo[(size_t)DM*DI];

// ===================== stable-PTX MMA helpers (sm_80+) ====================
__device__ __forceinline__ uint32_t smem_u32(const void* p) {
  uint32_t a;
  asm("{ .reg .u64 t; cvta.to.shared.u64 t, %1; cvt.u32.u64 %0, t; }"
      : "=r"(a) : "l"(p));
  return a;
}
#define LDSM_X4(r, addr) \
  asm volatile("ldmatrix.sync.aligned.m8n8.x4.shared.b16 {%0,%1,%2,%3}, [%4];" \
               : "=r"((r)[0]), "=r"((r)[1]), "=r"((r)[2]), "=r"((r)[3]) : "r"(addr))
#define MMA16816(c, a, b0, b1) \
  asm volatile("mma.sync.aligned.m16n8k16.row.col.f32.bf16.bf16.f32 " \
               "{%0,%1,%2,%3}, {%4,%5,%6,%7}, {%8,%9}, {%0,%1,%2,%3};" \
               : "+f"((c)[0]), "+f"((c)[1]), "+f"((c)[2]), "+f"((c)[3]) \
               : "r"((a)[0]), "r"((a)[1]), "r"((a)[2]), "r"((a)[3]), \
                 "r"(b0), "r"(b1))

// ================= kernel 1: res=res+x, LayerNorm -> g_u ==================
__global__ __launch_bounds__(256) void add_ln_kernel(
    const float* __restrict__ x, const float* __restrict__ res,
    const float* __restrict__ gamma, const float* __restrict__ beta,
    float* __restrict__ res_out) {
  int row = blockIdx.x;
  int tid = threadIdx.x;
  const float* xr = x   + (size_t)row * DM;
  const float* rr = res + (size_t)row * DM;
  float v[3];
  float s = 0.f, ss = 0.f;
#pragma unroll
  for (int i = 0; i < 3; i++) {
    int c = tid + i * 256;
    float t = xr[c] + rr[c];
    v[i] = t; s += t; ss += t * t;
  }
  __shared__ float red0[8], red1[8];
#pragma unroll
  for (int o = 16; o; o >>= 1) {
    s  += __shfl_xor_sync(0xffffffffu, s,  o);
    ss += __shfl_xor_sync(0xffffffffu, ss, o);
  }
  if ((tid & 31) == 0) { red0[tid >> 5] = s; red1[tid >> 5] = ss; }
  __syncthreads();
  if (tid < 32) {
    float a = (tid < 8) ? red0[tid] : 0.f;
    float b = (tid < 8) ? red1[tid] : 0.f;
#pragma unroll
    for (int o = 4; o; o >>= 1) {
      a += __shfl_xor_sync(0xffffffffu, a, o);
      b += __shfl_xor_sync(0xffffffffu, b, o);
    }
    if (tid == 0) { red0[0] = a; red1[0] = b; }
  }
  __syncthreads();
  float mean = red0[0] * (1.f / DM);
  float var  = red1[0] * (1.f / DM) - mean * mean;
  float rstd = rsqrtf(var + 1e-5f);
  float* ro = res_out + (size_t)row * DM;
  float* uo = g_u     + (size_t)row * DM;
#pragma unroll
  for (int i = 0; i < 3; i++) {
    int c = tid + i * 256;
    ro[c] = v[i];
    uo[c] = (v[i] - mean) * rstd * gamma[c] + beta[c];
  }
}

// ======= split fp32 -> bf16 hi/lo (sel: 0=u, 1=W_in, 2=yg, 3=W_out) =======
__global__ __launch_bounds__(256) void split_bf16_kernel(
    const float* __restrict__ src, int sel, int n4) {
  const float* s;
  __nv_bfloat16 *hi, *lo;
  if      (sel == 0) { s = g_u;  hi = g_uhi;    lo = g_ulo;    }
  else if (sel == 1) { s = src;  hi = g_winhi;  lo = g_winlo;  }
  else if (sel == 2) { s = g_yg; hi = g_yghi;   lo = g_yglo;   }
  else               { s = src;  hi = g_wouthi; lo = g_woutlo; }
  int i = blockIdx.x * 256 + threadIdx.x;
  if (i >= n4) return;
  float4 v = ((const float4*)s)[i];
  union { __nv_bfloat16 b[4]; uint2 u; } H, L;
  H.b[0] = __float2bfloat16(v.x); L.b[0] = __float2bfloat16(v.x - __bfloat162float(H.b[0]));
  H.b[1] = __float2bfloat16(v.y); L.b[1] = __float2bfloat16(v.y - __bfloat162float(H.b[1]));
  H.b[2] = __float2bfloat16(v.z); L.b[2] = __float2bfloat16(v.z - __bfloat162float(H.b[2]));
  H.b[3] = __float2bfloat16(v.w); L.b[3] = __float2bfloat16(v.w - __bfloat162float(H.b[3]));
  ((uint2*)hi)[i] = H.u;
  ((uint2*)lo)[i] = L.u;
}

// ========= mma.sync bf16x3-split GEMM: C[M,N] = A[M,K] @ B[N,K]^T =========
// Block tile 128x128, 8 warps (4 M x 2 N), warp tile 32x64, K-chunk 32.
// SMEM rows padded to 40 bf16 (80 B): 20*r mod 32 is distinct for any 8
// consecutive rows -> conflict-free ldmatrix without XOR swizzle.
// 3 passes per K-step: Ah*Bh + Al*Bh + Ah*Bl (hi/lo bf16 split).
#define SROW 40
__global__ __launch_bounds__(256) void gemm_mma_bf16x3(
    int which, float* __restrict__ Cdir, int Ntot, int K) {
  const __nv_bfloat16 *Ah, *Al, *Bh, *Bl;
  float* C;
  if (which == 0) { Ah = g_uhi;  Al = g_ulo;  Bh = g_winhi;  Bl = g_winlo;  C = g_xz; }
  else            { Ah = g_yghi; Al = g_yglo; Bh = g_wouthi; Bl = g_woutlo; C = Cdir; }

  __shared__ __align__(16) __nv_bfloat16 sAh[128 * SROW];
  __shared__ __align__(16) __nv_bfloat16 sAl[128 * SROW];
  __shared__ __align__(16) __nv_bfloat16 sBh[128 * SROW];
  __shared__ __align__(16) __nv_bfloat16 sBl[128 * SROW];

  int tid  = threadIdx.x;
  int lane = tid & 31;
  int warp = tid >> 5;
  int wm   = warp >> 1;          // 0..3: 32-row strip
  int wn   = warp & 1;           // 0..1: 64-col strip
  int bm   = blockIdx.y << 7;
  int bn   = blockIdx.x << 7;

  uint32_t baAh = smem_u32(sAh), baAl = smem_u32(sAl);
  uint32_t baBh = smem_u32(sBh), baBl = smem_u32(sBl);

  // ldmatrix per-lane byte offsets (row*80 + chunk*16), constant across k
  uint32_t aoff[2], boff[4];
#pragma unroll
  for (int mt = 0; mt < 2; mt++)
    aoff[mt] = (uint32_t)(wm * 32 + mt * 16 + (lane & 15)) * 80 + (lane >> 4) * 16;
#pragma unroll
  for (int p = 0; p < 4; p++)
    boff[p] = (uint32_t)(wn * 64 + p * 16 + (lane & 7) + ((lane >> 4) << 3)) * 80 +
              ((lane >> 3) & 1) * 16;

  float acc[2][8][4];
#pragma unroll
  for (int mt = 0; mt < 2; mt++)
#pragma unroll
    for (int nt = 0; nt < 8; nt++)
#pragma unroll
      for (int q = 0; q < 4; q++) acc[mt][nt][q] = 0.f;

  // global<->smem tile indices: each thread moves 2 uint4 per tile per chunk
  int i0 = tid, i1 = tid + 256;
  int r0 = i0 >> 2, c0 = i0 & 3, r1 = i1 >> 2, c1 = i1 & 3;
  int so0 = r0 * SROW + c0 * 8, so1 = r1 * SROW + c1 * 8;

  uint4 vAh0, vAh1, vAl0, vAl1, vBh0, vBh1, vBl0, vBl1;
  {
    size_t ga0 = (size_t)(bm + r0) * K + c0 * 8;
    size_t ga1 = (size_t)(bm + r1) * K + c1 * 8;
    size_t gb0 = (size_t)(bn + r0) * K + c0 * 8;
    size_t gb1 = (size_t)(bn + r1) * K + c1 * 8;
    vAh0 = *(const uint4*)(Ah + ga0); vAh1 = *(const uint4*)(Ah + ga1);
    vAl0 = *(const uint4*)(Al + ga0); vAl1 = *(const uint4*)(Al + ga1);
    vBh0 = *(const uint4*)(Bh + gb0); vBh1 = *(const uint4*)(Bh + gb1);
    vBl0 = *(const uint4*)(Bl + gb0); vBl1 = *(const uint4*)(Bl + gb1);
  }
  *(uint4*)&sAh[so0] = vAh0; *(uint4*)&sAh[so1] = vAh1;
  *(uint4*)&sAl[so0] = vAl0; *(uint4*)&sAl[so1] = vAl1;
  *(uint4*)&sBh[so0] = vBh0; *(uint4*)&sBh[so1] = vBh1;
  *(uint4*)&sBl[so0] = vBl0; *(uint4*)&sBl[so1] = vBl1;

  int nchunks = K >> 5;
  for (int kc = 0; kc < nchunks; kc++) {
    __syncthreads();
    // prefetch next chunk into registers (latency hidden behind the mmas)
    if (kc + 1 < nchunks) {
      int k0 = (kc + 1) << 5;
      size_t ga0 = (size_t)(bm + r0) * K + k0 + c0 * 8;
      size_t ga1 = (size_t)(bm + r1) * K + k0 + c1 * 8;
      size_t gb0 = (size_t)(bn + r0) * K + k0 + c0 * 8;
      size_t gb1 = (size_t)(bn + r1) * K + k0 + c1 * 8;
      vAh0 = *(const uint4*)(Ah + ga0); vAh1 = *(const uint4*)(Ah + ga1);
      vAl0 = *(const uint4*)(Al + ga0); vAl1 = *(const uint4*)(Al + ga1);
      vBh0 = *(const uint4*)(Bh + gb0); vBh1 = *(const uint4*)(Bh + gb1);
      vBl0 = *(const uint4*)(Bl + gb0); vBl1 = *(const uint4*)(Bl + gb1);
    }
#pragma unroll
    for (int ks = 0; ks < 2; ks++) {
      uint32_t ah[2][4], al[2][4], bh[4][4], bl[4][4];
#pragma unroll
      for (int mt = 0; mt < 2; mt++) {
        LDSM_X4(ah[mt], baAh + aoff[mt] + ks * 32);
        LDSM_X4(al[mt], baAl + aoff[mt] + ks * 32);
      }
#pragma unroll
      for (int p = 0; p < 4; p++) {
        LDSM_X4(bh[p], baBh + boff[p] + ks * 32);
        LDSM_X4(bl[p], baBl + boff[p] + ks * 32);
      }
#pragma unroll
      for (int mt = 0; mt < 2; mt++)
#pragma unroll
        for (int nt = 0; nt < 8; nt++) {
          uint32_t b0h = bh[nt >> 1][(nt & 1) * 2], b1h = bh[nt >> 1][(nt & 1) * 2 + 1];
          uint32_t b0l = bl[nt >> 1][(nt & 1) * 2], b1l = bl[nt >> 1][(nt & 1) * 2 + 1];
          MMA16816(acc[mt][nt], ah[mt], b0h, b1h);   // hi*hi
          MMA16816(acc[mt][nt], al[mt], b0h, b1h);   // lo*hi
          MMA16816(acc[mt][nt], ah[mt], b0l, b1l);   // hi*lo
        }
    }
    __syncthreads();
    if (kc + 1 < nchunks) {
      *(uint4*)&sAh[so0] = vAh0; *(uint4*)&sAh[so1] = vAh1;
      *(uint4*)&sAl[so0] = vAl0; *(uint4*)&sAl[so1] = vAl1;
      *(uint4*)&sBh[so0] = vBh0; *(uint4*)&sBh[so1] = vBh1;
      *(uint4*)&sBl[so0] = vBl0; *(uint4*)&sBl[so1] = vBl1;
    }
  }

  // epilogue: fragment layout -> C
#pragma unroll
  for (int mt = 0; mt < 2; mt++) {
    int rr0 = bm + wm * 32 + mt * 16 + (lane >> 2);
#pragma unroll
    for (int nt = 0; nt < 8; nt++) {
      int cc = bn + wn * 64 + nt * 8 + (lane & 3) * 2;
      *(float2*)(C + (size_t)rr0 * Ntot + cc) =
          make_float2(acc[mt][nt][0], acc[mt][nt][1]);
      *(float2*)(C + (size_t)(rr0 + 8) * Ntot + cc) =
          make_float2(acc[mt][nt][2], acc[mt][nt][3]);
    }
  }
}

// ============ kernel 3: causal depthwise conv1d (k=4) + SiLU ==============
__global__ __launch_bounds__(256) void conv_silu_kernel(
    const float* __restrict__ cw, const float* __restrict__ cb) {
  int d  = blockIdx.y * 256 + threadIdx.x;
  int ch = blockIdx.x;
  int b  = ch >> 7;
  int t0 = (ch & 127) << 4;
  float w0 = cw[d * 4 + 0], w1 = cw[d * 4 + 1];
  float w2 = cw[d * 4 + 2], w3 = cw[d * 4 + 3];
  float bb = cb[d];
  size_t base = ((size_t)b * SEQ) * (2 * DI) + d;
  float xm3 = (t0 >= 3) ? g_xz[base + (size_t)(t0 - 3) * (2 * DI)] : 0.f;
  float xm2 = (t0 >= 2) ? g_xz[base + (size_t)(t0 - 2) * (2 * DI)] : 0.f;
  float xm1 = (t0 >= 1) ? g_xz[base + (size_t)(t0 - 1) * (2 * DI)] : 0.f;
#pragma unroll
  for (int i = 0; i < 16; i++) {
    int t = t0 + i;
    float xt = g_xz[base + (size_t)t * (2 * DI)];
    float a  = w0 * xm3 + w1 * xm2 + w2 * xm1 + w3 * xt + bb;
    float sg = 1.f / (1.f + __expf(-a));
    g_xc[((size_t)b * SEQ + t) * DI + d] = a * sg;
    xm3 = xm2; xm2 = xm1; xm1 = xt;
  }
}

// ====== kernel 4: x_proj: proj[M,80] = xc[M,1536] @ W_xproj[80,1536]^T ====
__global__ __launch_bounds__(256) void xproj_kernel(
    const float* __restrict__ W) {
  __shared__ float sA[64][17];
  __shared__ float sB[80][17];
  int tid = threadIdx.x;
  int tx = tid & 15, ty = tid >> 4;
  int bm = blockIdx.x * 64;
  int kk = tid & 15, r = tid >> 4;
  float acc[4][5];
#pragma unroll
  for (int i = 0; i < 4; i++)
#pragma unroll
    for (int j = 0; j < 5; j++) acc[i][j] = 0.f;

  for (int k0 = 0; k0 < DI; k0 += 16) {
#pragma unroll
    for (int p = 0; p < 4; p++)
      sA[r + 16 * p][kk] = g_xc[(size_t)(bm + r + 16 * p) * DI + k0 + kk];
#pragma unroll
    for (int q = 0; q < 5; q++)
      sB[r + 16 * q][kk] = W[(size_t)(r + 16 * q) * DI + k0 + kk];
    __syncthreads();
#pragma unroll
    for (int k = 0; k < 16; k++) {
      float ra[4], rb[5];
#pragma unroll
      for (int i = 0; i < 4; i++) ra[i] = sA[ty * 4 + i][k];
#pragma unroll
      for (int j = 0; j < 5; j++) rb[j] = sB[tx + 16 * j][k];
#pragma unroll
      for (int i = 0; i < 4; i++)
#pragma unroll
        for (int j = 0; j < 5; j++)
          acc[i][j] = fmaf(ra[i], rb[j], acc[i][j]);
    }
    __syncthreads();
  }
#pragma unroll
  for (int i = 0; i < 4; i++)
#pragma unroll
    for (int j = 0; j < 5; j++)
      g_proj[(size_t)(bm + ty * 4 + i) * NPROJ + tx + 16 * j] = acc[i][j];
}

// == kernel 5: dt[M,1536] = softplus(proj[:,0:48] @ W_dt[1536,48]^T + b_dt) =
__global__ __launch_bounds__(256) void dtproj_kernel(
    const float* __restrict__ Wdt, const float* __restrict__ bdt) {
  __shared__ float sA[64][49];
  __shared__ float sW[64][49];
  int tid = threadIdx.x;
  int tx = tid & 15, ty = tid >> 4;
  int bm = blockIdx.y * 64, bn = blockIdx.x * 64;
  for (int i = tid; i < 64 * 48; i += 256) {
    int r2 = i / 48, k = i % 48;
    sA[r2][k] = g_proj[(size_t)(bm + r2) * NPROJ + k];
    sW[r2][k] = Wdt[(size_t)(bn + r2) * DR + k];
  }
  __syncthreads();
  float acc[4][4];
#pragma unroll
  for (int i = 0; i < 4; i++)
#pragma unroll
    for (int j = 0; j < 4; j++) acc[i][j] = 0.f;
#pragma unroll 8
  for (int k = 0; k < 48; k++) {
    float ra[4], rb[4];
#pragma unroll
    for (int i = 0; i < 4; i++) ra[i] = sA[ty * 4 + i][k];
#pragma unroll
    for (int j = 0; j < 4; j++) rb[j] = sW[tx * 4 + j][k];
#pragma unroll
    for (int i = 0; i < 4; i++)
#pragma unroll
      for (int j = 0; j < 4; j++)
        acc[i][j] = fmaf(ra[i], rb[j], acc[i][j]);
  }
#pragma unroll
  for (int i = 0; i < 4; i++)
#pragma unroll
    for (int j = 0; j < 4; j++) {
      int col = bn + tx * 4 + j;
      float v = acc[i][j] + bdt[col];
      v = (v > 20.f) ? v : log1pf(__expf(v));
      g_dt[(size_t)(bm + ty * 4 + i) * DI + col] = v;
    }
}

// ================= kernel 6: selective scan + gating ======================
#define SCAN_TT 64
__global__ __launch_bounds__(128) void scan_kernel(
    const float* __restrict__ A_log, const float* __restrict__ Dw) {
  int d = blockIdx.x * 128 + threadIdx.x;
  int b = blockIdx.y;
  int tid = threadIdx.x;
  __shared__ float sBC[SCAN_TT][32];

  float a[DS];
#pragma unroll
  for (int n = 0; n < DS; n++) a[n] = -expf(A_log[(size_t)d * DS + n]);
  float Dv = Dw[d];
  float h[DS];
#pragma unroll
  for (int n = 0; n < DS; n++) h[n] = 0.f;

  size_t di_base = ((size_t)b * SEQ) * DI + d;
  size_t z_base  = ((size_t)b * SEQ) * (2 * DI) + DI + d;

  float dt0 = g_dt[di_base],      x0 = g_xc[di_base],      z0 = g_xz[z_base];
  float dt1 = g_dt[di_base + DI], x1 = g_xc[di_base + DI], z1 = g_xz[z_base + 2 * DI];

  for (int t0 = 0; t0 < SEQ; t0 += SCAN_TT) {
    __syncthreads();
    for (int i = tid; i < SCAN_TT * 32; i += 128) {
      int tt = i >> 5, c = i & 31;
      sBC[tt][c] = g_proj[((size_t)b * SEQ + t0 + tt) * NPROJ + DR + c];
    }
    __syncthreads();
#pragma unroll 4
    for (int tt = 0; tt < SCAN_TT; tt++) {
      int t = t0 + tt;
      float dtc = dt0, xt = x0, zt = z0;
      dt0 = dt1; x0 = x1; z0 = z1;
      if (t + 2 < SEQ) {
        size_t o = di_base + (size_t)(t + 2) * DI;
        dt1 = g_dt[o];
        x1  = g_xc[o];
        z1  = g_xz[z_base + (size_t)(t + 2) * (2 * DI)];
      }
      float dtx = dtc * xt;
      float y0 = 0.f, y1 = 0.f;
#pragma unroll
      for (int n = 0; n < DS; n++) {
        float dA = __expf(dtc * a[n]);
        h[n] = h[n] * dA + dtx * sBC[tt][n];
        if (n & 1) y1 = fmaf(h[n], sBC[tt][16 + n], y1);
        else       y0 = fmaf(h[n], sBC[tt][16 + n], y0);
      }
      float y  = y0 + y1 + Dv * xt;
      float sg = 1.f / (1.f + __expf(-zt));
      g_yg[di_base + (size_t)t * DI] = y * (zt * sg);
    }
  }
}

// ================================ launch ==================================
extern "C" void kernel_launch(void* const* d_in, const int* in_sizes, int n_in,
                              void* d_out, int out_size) {
  const float* x      = (const float*)d_in[0];
  const float* res    = (const float*)d_in[1];
  const float* gamma  = (const float*)d_in[2];
  const float* beta   = (const float*)d_in[3];
  const float* W_in   = (const float*)d_in[4];
  const float* conv_w = (const float*)d_in[5];
  const float* conv_b = (const float*)d_in[6];
  const float* W_xp   = (const float*)d_in[7];
  const float* W_dt   = (const float*)d_in[8];
  const float* b_dt   = (const float*)d_in[9];
  const float* A_log  = (const float*)d_in[10];
  const float* Dw     = (const float*)d_in[11];
  const float* W_out  = (const float*)d_in[12];

  float* outp    = (float*)d_out;                   // (B,L,DM)
  float* res_out = outp + (size_t)MROWS * DM;       // (B,L,DM)

  const int n4_u    = (MROWS * DM) / 4;
  const int n4_win  = (2 * DI * DM) / 4;
  const int n4_yg   = (MROWS * DI) / 4;
  const int n4_wout = (DM * DI) / 4;

  // 1) res = res + x ; u = LN(res)
  add_ln_kernel<<<MROWS, 256>>>(x, res, gamma, beta, res_out);
  // 2) bf16 hi/lo splits for in_proj operands
  split_bf16_kernel<<<n4_u   / 256, 256>>>(nullptr, 0, n4_u);
  split_bf16_kernel<<<n4_win / 256, 256>>>(W_in,    1, n4_win);
  // 3) xz = u @ W_in^T  (8192 x 3072 x 768) via mma.sync bf16x3
  gemm_mma_bf16x3<<<dim3((2 * DI) / 128, MROWS / 128), 256>>>(0, nullptr, 2 * DI, DM);
  // 4) xc = silu(causal_conv(xs))
  conv_silu_kernel<<<dim3(BATCH * SEQ / 16, DI / 256), 256>>>(conv_w, conv_b);
  // 5) proj = xc @ W_xproj^T
  xproj_kernel<<<MROWS / 64, 256>>>(W_xp);
  // 6) dt = softplus(proj[:,:48] @ W_dt^T + b_dt)
  dtproj_kernel<<<dim3(DI / 64, MROWS / 64), 256>>>(W_dt, b_dt);
  // 7) selective scan + D skip + silu(z) gating -> g_yg
  scan_kernel<<<dim3(DI / 128, BATCH), 128>>>(A_log, Dw);
  // 8) bf16 hi/lo splits for out_proj operands
  split_bf16_kernel<<<n4_yg   / 256, 256>>>(nullptr, 2, n4_yg);
  split_bf16_kernel<<<n4_wout / 256, 256>>>(W_out,   3, n4_wout);
  // 9) out = yg @ W_out^T  (8192 x 768 x 1536) via mma.sync bf16x3
  gemm_mma_bf16x3<<<dim3(DM / 128, MROWS / 128), 256>>>(1, outp, DM, DI);
}